// round 16
// baseline (speedup 1.0000x reference)
#include <cuda_runtime.h>
#include <cstdint>

#define TT 512
#define BB 1024
#define CC 64
#define FULLMASK 0xFFFFFFFFu
#define GRID 256
#define NWARP 4

typedef unsigned long long u64;

__device__ float g_part[BB];
__device__ int   g_lpart[8][BB];
__device__ int   g_len[BB];
__device__ int   g_order[BB];      // chain ids, descending length

// ---- packed f32x2 helpers ----
static __device__ __forceinline__ u64 fma2(u64 a, u64 b, u64 c) {
    u64 r;
    asm("fma.rn.f32x2 %0, %1, %2, %3;" : "=l"(r) : "l"(a), "l"(b), "l"(c));
    return r;
}
static __device__ __forceinline__ u64 add2(u64 a, u64 b) {
    u64 r;
    asm("add.rn.f32x2 %0, %1, %2;" : "=l"(r) : "l"(a), "l"(b));
    return r;
}
static __device__ __forceinline__ u64 pack2(float lo, float hi) {
    u64 r;
    asm("mov.b64 %0, {%1, %2};" : "=l"(r) : "f"(lo), "f"(hi));
    return r;
}
static __device__ __forceinline__ float hadd2(u64 a) {
    float lo, hi;
    asm("mov.b64 {%0, %1}, %2;" : "=f"(lo), "=f"(hi) : "l"(a));
    return lo + hi;
}

// ---- pre-pass 1: per-slice partial lengths (coalesced) ----
__global__ void crf_len(const float* __restrict__ mask) {
    const int b = threadIdx.x;
    const int k = blockIdx.x;
    float c = 0.0f;
#pragma unroll 8
    for (int t = k * 64; t < (k + 1) * 64; t++)
        c += mask[t * BB + b];
    g_lpart[k][b] = (int)c;
}

// ---- pre-pass 2: counting sort by length, descending ----
__global__ void crf_sort() {
    __shared__ int hist[TT + 1];
    __shared__ int off[TT + 1];
    const int b = threadIdx.x;
    if (b <= TT) hist[b] = 0;
    __syncthreads();
    int len = 0;
#pragma unroll
    for (int k = 0; k < 8; k++) len += g_lpart[k][b];
    g_len[b] = len;
    atomicAdd(&hist[len], 1);
    __syncthreads();
    if (b == 0) {
        int acc = 0;
        for (int l = TT; l >= 0; l--) { off[l] = acc; acc += hist[l]; }
    }
    __syncthreads();
    const int r = atomicAdd(&off[len], 1);
    g_order[r] = b;
}

// One warp per chain. 4-warp blocks, 3 blocks/SM (launch_bounds) -> 3 warps
// per SMSP of latency cover. Block bl's warps take sorted ranks
// {bl, 511-bl, 512+bl, 1023-bl}: two long + two short per block.
__global__ void __launch_bounds__(NWARP * 32, 3) crf_chain(
    const float* __restrict__ h,      // (T, B, C)
    const int*   __restrict__ y0,     // (T+1, B)
    const float* __restrict__ mask,   // unused
    const float* __restrict__ trans)  // (C, C)
{
    __shared__ __align__(16) float tr_sh[CC * CC];
    __shared__ __align__(16) float E_sh[CC * CC];          // exp(trans)
    __shared__ __align__(16) u64   p_sh[NWARP][2][32];

    const int tid  = threadIdx.x;
    const int lane = tid & 31;
    const int wid  = tid >> 5;

    // chain id loads issued early (latency hidden under smem fill)
    const int bl = blockIdx.x;
    int rank;
    switch (wid) {
        case 0:  rank = bl;          break;
        case 1:  rank = 511 - bl;    break;
        case 2:  rank = 512 + bl;    break;
        default: rank = 1023 - bl;   break;
    }
    const int b   = g_order[rank];
    const int len = g_len[b];

    // cooperative fill: trans -> tr_sh, exp(trans) -> E_sh
    {
        const float4* g4 = (const float4*)trans;
        float4*       t4 = (float4*)tr_sh;
        float4*       e4 = (float4*)E_sh;
#pragma unroll
        for (int k = 0; k < (CC * CC / 4) / (NWARP * 32); k++) {
            const int    idx = tid + NWARP * 32 * k;
            const float4 v   = g4[idx];
            t4[idx] = v;
            float4 e;
            e.x = __expf(v.x); e.y = __expf(v.y);
            e.z = __expf(v.z); e.w = __expf(v.w);
            e4[idx] = e;
        }
    }
    __syncthreads();

    const int j0 = 2 * lane;
    const int j1 = 2 * lane + 1;

    // E rows -> registers as packed f32x2 pairs
    u64 e0[32], e1[32];
    {
        const ulonglong2* ge = (const ulonglong2*)E_sh;
#pragma unroll
        for (int k = 0; k < 16; k++) {
            ulonglong2 q0 = ge[j0 * 16 + k];
            ulonglong2 q1 = ge[j1 * 16 + k];
            e0[2 * k] = q0.x; e0[2 * k + 1] = q0.y;
            e1[2 * k] = q1.x; e1[2 * k + 1] = q1.y;
        }
    }

    // init: v one-hot at SOS(=1); Ccum = 0; normalizer seeded to 1
    float pc0 = (j0 == 1) ? 1.0f : 0.0f;
    float pc1 = (j1 == 1) ? 1.0f : 0.0f;
    float nrm_reg = 1.0f;     // lane 1's copy tracks v[3]
    float Ccum = 0.0f;
    p_sh[wid][0][lane] = pack2(pc0, pc1);
    __syncwarp();

    // 8-deep indexed h ring (float2/lane/step), slot = t & 7
    const float2* hp   = (const float2*)h;
    const int     HROW = BB * CC / 2;
    const int     hoff = b * (CC / 2) + lane;
    float2 hb[8];
#pragma unroll
    for (int k = 0; k < 8; k++) hb[k] = hp[(size_t)k * HROW + hoff];

    int buf = 0;

    // one step; s = static ring slot; norm every 4 steps (range-safe:
    // growth <= e^32 between norms, spread <= e^15, inside fp32).
    // 4-way accumulator tree (R9 proven; minimal registers).
    auto step = [&](int tcur, int s, bool do_norm) __attribute__((always_inline)) {
        const float2 hc  = hb[s];
        float r = 1.0f;
        if (do_norm) {
            const float nrm = __shfl_sync(FULLMASK, nrm_reg, 1);
            r = __fdividef(1.0f, nrm);
            Ccum += __logf(nrm);
        }
        const float eh0 = __expf(hc.x);
        const float eh1 = __expf(hc.y);

        const ulonglong2* pv = (const ulonglong2*)p_sh[wid][buf];
        u64 a0[4] = {0, 0, 0, 0};
        u64 a1[4] = {0, 0, 0, 0};
#pragma unroll
        for (int k = 0; k < 16; k++) {
            ulonglong2 q = pv[k];
            const int  c = 2 * (k & 1);
            a0[c]     = fma2(e0[2 * k],     q.x, a0[c]);
            a0[c + 1] = fma2(e0[2 * k + 1], q.y, a0[c + 1]);
            a1[c]     = fma2(e1[2 * k],     q.x, a1[c]);
            a1[c + 1] = fma2(e1[2 * k + 1], q.y, a1[c + 1]);
        }
        const float acc0 = hadd2(add2(add2(a0[0], a0[1]), add2(a0[2], a0[3])));
        const float acc1 = hadd2(add2(add2(a1[0], a1[1]), add2(a1[2], a1[3])));

        if (do_norm) { pc0 = acc0 * r * eh0; pc1 = acc1 * r * eh1; }
        else         { pc0 = acc0 * eh0;     pc1 = acc1 * eh1;     }
        nrm_reg = pc1;                        // lane 1's pc1 == v[3]
        p_sh[wid][buf ^ 1][lane] = pack2(pc0, pc1);
        buf ^= 1;

        int tf = tcur + 8;
        if (tf > TT - 1) tf = TT - 1;
        hb[s] = hp[(size_t)tf * HROW + hoff];
        __syncwarp();
    };

    // counted main loop, then break-able tail chunk (warp-private control flow)
    const int len8 = len & ~7;
    int t = 0;
#pragma unroll 1
    for (; t < len8; t += 8) {
#pragma unroll
        for (int s = 0; s < 8; s++) step(t + s, s, (s & 3) == 0);
    }
#pragma unroll
    for (int s = 0; s < 8; s++) {
        if (t + s >= len) break;
        step(t + s, s, (s & 3) == 0);
    }

    // final: Zf = Ccum + log( sum_j v_j * exp(trans[EOS, j]) )
    float v = pc0 * E_sh[2 * CC + j0] + pc1 * E_sh[2 * CC + j1];
#pragma unroll
    for (int o = 16; o; o >>= 1) v += __shfl_xor_sync(FULLMASK, v, o);
    const float zf = Ccum + __logf(v);

    // score: S = sum_{t<min(len,T-1)} h[t,b,y0[t+1]] + trans[y0[t+1],y0[t]]
    float S = 0.0f;
    {
        const int tmax = (len < TT - 1) ? len : (TT - 1);
#pragma unroll
        for (int k = 0; k < 16; k++) {
            const int tt = lane + 32 * k;
            if (tt < tmax) {
                const int ya = y0[tt * BB + b];
                const int yb = y0[(tt + 1) * BB + b];
                const float hv = h[(size_t)tt * (BB * CC) + b * CC + yb];
                S += hv + tr_sh[yb * CC + ya];
            }
        }
#pragma unroll
        for (int o = 16; o; o >>= 1) S += __shfl_xor_sync(FULLMASK, S, o);
    }

    if (lane == 0) {
        const int last = y0[len * BB + b];
        g_part[b] = zf - (S + tr_sh[0 * CC + last]);   // trans[PAD, last]
    }
}

// Deterministic tree reduction of the 1024 per-chain results.
__global__ void crf_reduce(float* __restrict__ out) {
    __shared__ float sh[256];
    const int t = threadIdx.x;
    float s = 0.0f;
#pragma unroll
    for (int k = 0; k < 4; k++) s += g_part[t + 256 * k];
    sh[t] = s;
    __syncthreads();
    for (int o = 128; o; o >>= 1) {
        if (t < o) sh[t] += sh[t + o];
        __syncthreads();
    }
    if (t == 0) out[0] = sh[0] * (1.0f / 1024.0f);
}

extern "C" void kernel_launch(void* const* d_in, const int* in_sizes, int n_in,
                              void* d_out, int out_size) {
    const float* h     = nullptr;
    const int*   y0    = nullptr;
    const float* mask  = nullptr;
    const float* trans = nullptr;
    for (int i = 0; i < n_in; i++) {
        const long n = (long)in_sizes[i];
        if      (n == (long)TT * BB * CC)  h     = (const float*)d_in[i];
        else if (n == (long)(TT + 1) * BB) y0    = (const int*)d_in[i];
        else if (n == (long)TT * BB)       mask  = (const float*)d_in[i];
        else if (n == (long)CC * CC)       trans = (const float*)d_in[i];
    }

    crf_len<<<8, BB>>>(mask);
    crf_sort<<<1, BB>>>();
    crf_chain<<<GRID, NWARP * 32>>>(h, y0, mask, trans);
    crf_reduce<<<1, 256>>>((float*)d_out);
}

// round 17
// speedup vs baseline: 1.3724x; 1.3724x over previous
#include <cuda_runtime.h>
#include <cstdint>

#define TT 512
#define BB 1024
#define CC 64
#define FULLMASK 0xFFFFFFFFu
#define GRID 148
#define NWARP 8

typedef unsigned long long u64;

__device__ float g_part[BB];
__device__ int   g_lpart[8][BB];
__device__ int   g_len[BB];
__device__ int   g_order[BB];      // chain ids, descending length
__device__ int   g_done_len   = 0; // last-block-done counters (reset after use)
__device__ int   g_done_chain = 0;

// ---- packed f32x2 helpers ----
static __device__ __forceinline__ u64 fma2(u64 a, u64 b, u64 c) {
    u64 r;
    asm("fma.rn.f32x2 %0, %1, %2, %3;" : "=l"(r) : "l"(a), "l"(b), "l"(c));
    return r;
}
static __device__ __forceinline__ u64 add2(u64 a, u64 b) {
    u64 r;
    asm("add.rn.f32x2 %0, %1, %2;" : "=l"(r) : "l"(a), "l"(b));
    return r;
}
static __device__ __forceinline__ u64 pack2(float lo, float hi) {
    u64 r;
    asm("mov.b64 %0, {%1, %2};" : "=l"(r) : "f"(lo), "f"(hi));
    return r;
}
static __device__ __forceinline__ float hadd2(u64 a) {
    float lo, hi;
    asm("mov.b64 {%0, %1}, %2;" : "=f"(lo), "=f"(hi) : "l"(a));
    return lo + hi;
}

// ---- pass 1: per-slice lengths; LAST block also runs the counting sort ----
__global__ void crf_lensort(const float* __restrict__ mask) {
    const int b = threadIdx.x;            // 1024 threads
    const int k = blockIdx.x;             // 8 slices of 64 timesteps
    float c = 0.0f;
#pragma unroll 8
    for (int t = k * 64; t < (k + 1) * 64; t++)
        c += mask[t * BB + b];
    g_lpart[k][b] = (int)c;

    // last-block-done: the final block performs the sort
    __threadfence();
    __syncthreads();
    __shared__ int amLast;
    if (b == 0) {
        const int prev = atomicAdd(&g_done_len, 1);
        amLast = (prev == gridDim.x - 1);
    }
    __syncthreads();
    if (!amLast) return;

    __shared__ int hist[TT + 1];
    __shared__ int off[TT + 1];
    if (b <= TT) hist[b] = 0;
    __syncthreads();
    int len = 0;
#pragma unroll
    for (int q = 0; q < 8; q++) len += g_lpart[q][b];
    g_len[b] = len;
    atomicAdd(&hist[len], 1);
    __syncthreads();
    if (b == 0) {                         // descending exclusive offsets
        int acc = 0;
        for (int l = TT; l >= 0; l--) { off[l] = acc; acc += hist[l]; }
        g_done_len = 0;                   // reset for next graph replay
    }
    __syncthreads();
    const int r = atomicAdd(&off[len], 1);
    g_order[r] = b;
    __threadfence();                      // g_order/g_len visible before exit
}

// One warp per chain (R9-proven config: 8 warps/block, 148 blocks, band
// pairing long+short per SMSP). LAST block performs the final reduction.
__global__ void __launch_bounds__(NWARP * 32) crf_chain(
    const float* __restrict__ h,      // (T, B, C)
    const int*   __restrict__ y0,     // (T+1, B)
    const float* __restrict__ mask,   // unused
    const float* __restrict__ trans,  // (C, C)
    float* __restrict__ out)
{
    __shared__ __align__(16) float tr_sh[CC * CC];
    __shared__ __align__(16) float E_sh[CC * CC];          // exp(trans)
    __shared__ __align__(16) u64   p_sh[NWARP][2][32];

    const int tid  = threadIdx.x;
    const int lane = tid & 31;
    const int wid  = tid >> 5;

    // chain-id loads issued early (latency hidden under the smem fill)
    const int band = (wid < 4) ? wid : 11 - wid;
    const int rank = band * GRID + blockIdx.x;
    const bool active = (rank < BB);
    int b = 0, len = 0;
    if (active) {
        b   = g_order[rank];
        len = g_len[b];
    }

    // cooperative fill: trans -> tr_sh, exp(trans) -> E_sh
    {
        const float4* g4 = (const float4*)trans;
        float4*       t4 = (float4*)tr_sh;
        float4*       e4 = (float4*)E_sh;
#pragma unroll
        for (int k = 0; k < (CC * CC / 4) / (NWARP * 32); k++) {
            const int    idx = tid + NWARP * 32 * k;
            const float4 v   = g4[idx];
            t4[idx] = v;
            float4 e;
            e.x = __expf(v.x); e.y = __expf(v.y);
            e.z = __expf(v.z); e.w = __expf(v.w);
            e4[idx] = e;
        }
    }
    __syncthreads();

    if (active) {
        const int j0 = 2 * lane;
        const int j1 = 2 * lane + 1;

        // E rows -> registers as packed f32x2 pairs
        u64 e0[32], e1[32];
        {
            const ulonglong2* ge = (const ulonglong2*)E_sh;
#pragma unroll
            for (int k = 0; k < 16; k++) {
                ulonglong2 q0 = ge[j0 * 16 + k];
                ulonglong2 q1 = ge[j1 * 16 + k];
                e0[2 * k] = q0.x; e0[2 * k + 1] = q0.y;
                e1[2 * k] = q1.x; e1[2 * k + 1] = q1.y;
            }
        }

        // init: v one-hot at SOS(=1); Ccum = 0; normalizer seeded to 1
        float pc0 = (j0 == 1) ? 1.0f : 0.0f;
        float pc1 = (j1 == 1) ? 1.0f : 0.0f;
        float nrm_reg = 1.0f;     // lane 1's copy tracks v[3]
        float Ccum = 0.0f;
        p_sh[wid][0][lane] = pack2(pc0, pc1);
        __syncwarp();

        // 8-deep indexed h ring (float2/lane/step), slot = t & 7
        const float2* hp   = (const float2*)h;
        const int     HROW = BB * CC / 2;
        const int     hoff = b * (CC / 2) + lane;
        float2 hb[8];
#pragma unroll
        for (int k = 0; k < 8; k++) hb[k] = hp[(size_t)k * HROW + hoff];

        int buf = 0;

        // one step; s = static ring slot; norm every 4 steps (range-safe)
        auto step = [&](int tcur, int s, bool do_norm) __attribute__((always_inline)) {
            const float2 hc  = hb[s];
            float r = 1.0f;
            if (do_norm) {
                const float nrm = __shfl_sync(FULLMASK, nrm_reg, 1);
                r = __fdividef(1.0f, nrm);
                Ccum += __logf(nrm);
            }
            const float eh0 = __expf(hc.x);
            const float eh1 = __expf(hc.y);

            const ulonglong2* pv = (const ulonglong2*)p_sh[wid][buf];
            u64 a0[4] = {0, 0, 0, 0};
            u64 a1[4] = {0, 0, 0, 0};
#pragma unroll
            for (int k = 0; k < 16; k++) {
                ulonglong2 q = pv[k];
                const int  c = 2 * (k & 1);
                a0[c]     = fma2(e0[2 * k],     q.x, a0[c]);
                a0[c + 1] = fma2(e0[2 * k + 1], q.y, a0[c + 1]);
                a1[c]     = fma2(e1[2 * k],     q.x, a1[c]);
                a1[c + 1] = fma2(e1[2 * k + 1], q.y, a1[c + 1]);
            }
            const float acc0 = hadd2(add2(add2(a0[0], a0[1]), add2(a0[2], a0[3])));
            const float acc1 = hadd2(add2(add2(a1[0], a1[1]), add2(a1[2], a1[3])));

            if (do_norm) { pc0 = acc0 * r * eh0; pc1 = acc1 * r * eh1; }
            else         { pc0 = acc0 * eh0;     pc1 = acc1 * eh1;     }
            nrm_reg = pc1;                        // lane 1's pc1 == v[3]
            p_sh[wid][buf ^ 1][lane] = pack2(pc0, pc1);
            buf ^= 1;

            int tf = tcur + 8;
            if (tf > TT - 1) tf = TT - 1;
            hb[s] = hp[(size_t)tf * HROW + hoff];
            __syncwarp();
        };

        // counted main loop, then break-able tail chunk
        const int len8 = len & ~7;
        int t = 0;
#pragma unroll 1
        for (; t < len8; t += 8) {
#pragma unroll
            for (int s = 0; s < 8; s++) step(t + s, s, (s & 3) == 0);
        }
#pragma unroll
        for (int s = 0; s < 8; s++) {
            if (t + s >= len) break;
            step(t + s, s, (s & 3) == 0);
        }

        // final: Zf = Ccum + log( sum_j v_j * exp(trans[EOS, j]) )
        float v = pc0 * E_sh[2 * CC + j0] + pc1 * E_sh[2 * CC + j1];
#pragma unroll
        for (int o = 16; o; o >>= 1) v += __shfl_xor_sync(FULLMASK, v, o);
        const float zf = Ccum + __logf(v);

        // score: S = sum_{t<min(len,T-1)} h[t,b,y0[t+1]] + trans[y0[t+1],y0[t]]
        float S = 0.0f;
        {
            const int tmax = (len < TT - 1) ? len : (TT - 1);
#pragma unroll
            for (int k = 0; k < 16; k++) {
                const int tt = lane + 32 * k;
                if (tt < tmax) {
                    const int ya = y0[tt * BB + b];
                    const int yb = y0[(tt + 1) * BB + b];
                    const float hv = h[(size_t)tt * (BB * CC) + b * CC + yb];
                    S += hv + tr_sh[yb * CC + ya];
                }
            }
#pragma unroll
            for (int o = 16; o; o >>= 1) S += __shfl_xor_sync(FULLMASK, S, o);
        }

        if (lane == 0) {
            const int last = y0[len * BB + b];
            g_part[b] = zf - (S + tr_sh[0 * CC + last]);   // trans[PAD, last]
        }
    }

    // ---- last-block-done: deterministic fixed-order reduction ----
    __threadfence();
    __syncthreads();
    __shared__ int amLast;
    if (tid == 0) {
        const int prev = atomicAdd(&g_done_chain, 1);
        amLast = (prev == gridDim.x - 1);
    }
    __syncthreads();
    if (!amLast) return;

    {
        __shared__ float sh[256];
        if (tid < 256) {
            float s = 0.0f;
#pragma unroll
            for (int k = 0; k < 4; k++) s += g_part[tid + 256 * k];
            sh[tid] = s;
        }
        __syncthreads();
        for (int o = 128; o; o >>= 1) {
            if (tid < o) sh[tid] += sh[tid + o];
            __syncthreads();
        }
        if (tid == 0) {
            out[0] = sh[0] * (1.0f / 1024.0f);
            g_done_chain = 0;             // reset for next graph replay
        }
    }
}

extern "C" void kernel_launch(void* const* d_in, const int* in_sizes, int n_in,
                              void* d_out, int out_size) {
    const float* h     = nullptr;
    const int*   y0    = nullptr;
    const float* mask  = nullptr;
    const float* trans = nullptr;
    for (int i = 0; i < n_in; i++) {
        const long n = (long)in_sizes[i];
        if      (n == (long)TT * BB * CC)  h     = (const float*)d_in[i];
        else if (n == (long)(TT + 1) * BB) y0    = (const int*)d_in[i];
        else if (n == (long)TT * BB)       mask  = (const float*)d_in[i];
        else if (n == (long)CC * CC)       trans = (const float*)d_in[i];
    }

    crf_lensort<<<8, BB>>>(mask);
    crf_chain<<<GRID, NWARP * 32>>>(h, y0, mask, trans, (float*)d_out);
}